// round 14
// baseline (speedup 1.0000x reference)
#include <cuda_runtime.h>
#include <cuda_bf16.h>
#include <cstdint>

// 21x21 circular box filter on (8,1,2048,2048) fp32, separable, fused.
// Phase A: vertical running box-sums global -> smem, thread per halo column
//          (276 of 320 active, aligned warp loads via CSHIFT=22),
//          21-deep register ring (each input row loaded once per column).
// Phase B: horizontal box-sums via warp prefix scan per 128-col chunk
//          (64 tasks over 10 warps), direct float4 stores.

#define H  2048
#define W  2048
#define NB 8
#define R  10
#define KW (2*R + 1)        // 21
#define TX 256
#define TY 32
#define NC (TX + 2*R)       // 276 halo columns
#define CSHIFT 22           // thread t -> column t-22: warp loads line-aligned
#define VS 280              // smem row stride (floats), 16B-aligned
#define THREADS 320
#define NWARPS (THREADS/32)

__global__ __launch_bounds__(THREADS, 5)
void box_filter_kernel(const float* __restrict__ in, float* __restrict__ out)
{
    __shared__ float vert[TY * VS];   // 32*280*4 = 35,840 B

    const int t  = threadIdx.x;
    const int bx = blockIdx.x;
    const int by = blockIdx.y;
    const int bz = blockIdx.z;

    const float* img  = in  + (size_t)bz * (size_t)(H * W);
    float*       outg = out + (size_t)bz * (size_t)(H * W);

    const int tileX = bx * TX;
    const int tileY = by * TY;

    // ---------------- Phase A: vertical running sums (global -> smem) ---------
    // Column c = t - 22 (c in [0,276)); gx = tileX + t - 32 -> every warp's LDG
    // is one aligned 128B line. Ring buffer: 52 rows, each loaded exactly once.
    if (t >= CSHIFT && t < CSHIFT + NC) {
        const int c  = t - CSHIFT;
        const int gx = (tileX + c - R) & (W - 1);
        const int y0 = tileY - R;
        const float* colp = img + gx;

        float buf[KW];
        float s = 0.0f;

        if (y0 >= 0 && y0 + TY + 2 * R <= H) {
            // Interior: wrap-free, immediate offsets off one base pointer.
            const float* p = colp + (size_t)y0 * W;

            #pragma unroll
            for (int j = 0; j < KW; j++) { buf[j] = p[j * W]; s += buf[j]; }
            vert[c] = s;

            #pragma unroll
            for (int i = 1; i < TY; i++) {
                const int slot = (i - 1) % KW;       // compile-time after unroll
                const float nv = p[(i + 2 * R) * W];
                s += nv - buf[slot];
                buf[slot] = nv;
                vert[i * VS + c] = s;
            }
        } else {
            // Boundary tiles (by==0 or by==63): masked row addressing.
            #pragma unroll
            for (int j = 0; j < KW; j++) {
                buf[j] = colp[((y0 + j) & (H - 1)) * W];
                s += buf[j];
            }
            vert[c] = s;

            #pragma unroll
            for (int i = 1; i < TY; i++) {
                const int slot = (i - 1) % KW;
                const float nv = colp[((y0 + 2 * R + i) & (H - 1)) * W];
                s += nv - buf[slot];
                buf[slot] = nv;
                vert[i * VS + c] = s;
            }
        }
    }
    __syncthreads();

    // ---------------- Phase B: horizontal sums via warp scan, direct store ----
    // 64 tasks = 32 rows x 2 chunks of 128 outputs; warp per task.
    // Chunk data a[k] = vert[r][b+k], k=0..147; out[m] = P[m+21]-P[m].
    const unsigned FULL = 0xffffffffu;
    const int lane = t & 31;
    const int wp   = t >> 5;

    #pragma unroll 2
    for (int k = wp; k < 2 * TY; k += NWARPS) {
        const int r = k >> 1;
        const int b = (k & 1) << 7;            // 0 or 128
        const float* row = vert + r * VS + b;

        float4 q = *reinterpret_cast<const float4*>(row + 4 * lane);
        float  e = (lane < 20) ? row[128 + lane] : 0.0f;

        const float s1 = q.x;
        const float s2 = s1 + q.y;
        const float s3 = s2 + q.z;
        const float s4 = s3 + q.w;

        // inclusive scan of quad totals -> v;  B = P[4*lane]
        float v = s4;
        #pragma unroll
        for (int d = 1; d < 32; d <<= 1) {
            float u = __shfl_up_sync(FULL, v, d);
            if (lane >= d) v += u;
        }
        const float B = v - s4;

        // inclusive scan of extras -> w  (w[l] = sum a[128..128+l])
        float w = e;
        #pragma unroll
        for (int d = 1; d < 32; d <<= 1) {
            float u = __shfl_up_sync(FULL, w, d);
            if (lane >= d) w += u;
        }
        const float P128 = __shfl_sync(FULL, v, 31);   // P[128]

        // P[4l+21+j] from lane l+5
        const float Bp  = __shfl_down_sync(FULL, B,  5);
        const float s1p = __shfl_down_sync(FULL, s1, 5);
        const float s2p = __shfl_down_sync(FULL, s2, 5);
        const float s3p = __shfl_down_sync(FULL, s3, 5);
        const float s4p = __shfl_down_sync(FULL, s4, 5);

        // tail (lanes 27..31): P[idx] = P128 + T[idx-128]
        const int base = 4 * (lane - 27);
        const float w0 = __shfl_sync(FULL, w, (base + 0) & 31);
        const float w1 = __shfl_sync(FULL, w, (base + 1) & 31);
        const float w2 = __shfl_sync(FULL, w, (base + 2) & 31);
        const float w3 = __shfl_sync(FULL, w, (base + 3) & 31);

        const bool tail = (lane >= 27);
        const float u0 = tail ? (P128 + w0) : (Bp + s1p);
        const float u1 = tail ? (P128 + w1) : (Bp + s2p);
        const float u2 = tail ? (P128 + w2) : (Bp + s3p);
        const float u3 = tail ? (P128 + w3) : (Bp + s4p);

        float4 o;
        o.x = u0 - B;
        o.y = u1 - (B + s1);
        o.z = u2 - (B + s2);
        o.w = u3 - (B + s3);

        *reinterpret_cast<float4*>(
            outg + (size_t)(tileY + r) * W + tileX + b + 4 * lane) = o;
    }
}

extern "C" void kernel_launch(void* const* d_in, const int* in_sizes, int n_in,
                              void* d_out, int out_size)
{
    const float* x = (const float*)d_in[0];
    float* out = (float*)d_out;

    dim3 grid(W / TX, H / TY, NB);   // (8, 64, 8) = 4096 blocks
    box_filter_kernel<<<grid, THREADS>>>(x, out);
}

// round 15
// speedup vs baseline: 1.3651x; 1.3651x over previous
#include <cuda_runtime.h>
#include <cuda_bf16.h>
#include <cstdint>

// 21x21 circular box filter on (8,1,2048,2048) fp32, separable, fused.
// Phase A: vertical running box-sums global -> smem (thread per halo column),
//          21-deep register ring (each input row loaded once); thread->column
//          map shifted by 22 so every warp's LDG is one aligned 128B line.
// Phase B: horizontal box-sums via direct sliding window: lane computes
//          outputs 4l..4l+3 from 6 aligned conflict-free LDS.128 (24 floats),
//          26 FADD, one STG.128. No shuffles, no staging.

#define H  2048
#define W  2048
#define NB 8
#define R  10
#define KW (2*R + 1)        // 21
#define TX 128
#define TY 32
#define NC (TX + 2*R)       // 148 halo columns
#define CSHIFT 22           // thread t -> column t-22: warp loads line-aligned
#define VS 152              // smem row stride (floats), 16B-aligned rows
#define THREADS 256

__global__ __launch_bounds__(THREADS, 6)
void box_filter_kernel(const float* __restrict__ in, float* __restrict__ out)
{
    __shared__ float vert[TY * VS];   // 32*152*4 = 19,456 B

    const int t  = threadIdx.x;
    const int bx = blockIdx.x;
    const int by = blockIdx.y;
    const int bz = blockIdx.z;

    const float* img  = in  + (size_t)bz * (size_t)(H * W);
    float*       outg = out + (size_t)bz * (size_t)(H * W);

    const int tileX = bx * TX;
    const int tileY = by * TY;

    // ---------------- Phase A: vertical running sums (global -> smem) ---------
    // Column c = t - 22 (c in [0,148)); gx = tileX + t - 32 -> warp w loads the
    // aligned 128B line [tileX - 32 + 32w, +32 floats). Ring buffer: each of the
    // 52 input rows loaded exactly once per column.
    if (t >= CSHIFT && t < CSHIFT + NC) {
        const int c  = t - CSHIFT;
        const int gx = (tileX + c - R) & (W - 1);
        const int y0 = tileY - R;
        const float* colp = img + gx;

        float buf[KW];
        float s = 0.0f;

        if (y0 >= 0 && y0 + TY + 2 * R <= H) {
            // Interior: wrap-free, immediate offsets off one base pointer.
            const float* p = colp + (size_t)y0 * W;

            #pragma unroll
            for (int j = 0; j < KW; j++) { buf[j] = p[j * W]; s += buf[j]; }
            vert[c] = s;

            #pragma unroll
            for (int i = 1; i < TY; i++) {
                const int slot = (i - 1) % KW;       // compile-time after unroll
                const float nv = p[(i + 2 * R) * W];
                s += nv - buf[slot];
                buf[slot] = nv;
                vert[i * VS + c] = s;
            }
        } else {
            // Boundary tiles (by==0 or by==63): masked row addressing.
            #pragma unroll
            for (int j = 0; j < KW; j++) {
                buf[j] = colp[((y0 + j) & (H - 1)) * W];
                s += buf[j];
            }
            vert[c] = s;

            #pragma unroll
            for (int i = 1; i < TY; i++) {
                const int slot = (i - 1) % KW;
                const float nv = colp[((y0 + 2 * R + i) & (H - 1)) * W];
                s += nv - buf[slot];
                buf[slot] = nv;
                vert[i * VS + c] = s;
            }
        }
    }
    __syncthreads();

    // ---------------- Phase B: horizontal sliding window (smem -> global) -----
    // Warp per row (8 warps x 4 rows). out[m] = sum vert[r][m..m+20].
    // Lane l does m = 4l..4l+3: needs cols 4l..4l+23 = quads l..l+5.
    // LDS.128 j: lane l -> addr 16*(l+j) (+row base): conflict-free.
    const int lane = t & 31;
    const int wp   = t >> 5;

    #pragma unroll
    for (int rr = 0; rr < TY / 8; rr++) {
        const int r = wp * (TY / 8) + rr;
        const float* rowp = vert + r * VS + 4 * lane;

        float e[24];
        #pragma unroll
        for (int j = 0; j < 6; j++) {
            const float4 q = *reinterpret_cast<const float4*>(rowp + 4 * j);
            e[4 * j + 0] = q.x;
            e[4 * j + 1] = q.y;
            e[4 * j + 2] = q.z;
            e[4 * j + 3] = q.w;
        }

        float s = e[0];
        #pragma unroll
        for (int j = 1; j <= 20; j++) s += e[j];

        float4 o;
        o.x = s;
        s += e[21] - e[0];  o.y = s;
        s += e[22] - e[1];  o.z = s;
        s += e[23] - e[2];  o.w = s;

        *reinterpret_cast<float4*>(
            outg + (size_t)(tileY + r) * W + tileX + 4 * lane) = o;
    }
}

extern "C" void kernel_launch(void* const* d_in, const int* in_sizes, int n_in,
                              void* d_out, int out_size)
{
    const float* x = (const float*)d_in[0];
    float* out = (float*)d_out;

    dim3 grid(W / TX, H / TY, NB);   // (16, 64, 8) = 8192 blocks
    box_filter_kernel<<<grid, THREADS>>>(x, out);
}